// round 17
// baseline (speedup 1.0000x reference)
#include <cuda_runtime.h>
#include <cuda_bf16.h>
#include <cstdint>

#define BB 4
#define LL 2048
#define DD 512
#define NLAY 2
#define EDIM 1024
#define NSTATE 16
#define RRANK 32
#define KCONV 4
#define MM (BB*LL)   // 8192 tokens
#define NCHUNK 16
#define CHLEN 128    // LL / NCHUNK

// ---------------- scratch (static device allocations) ---------------------------
__device__ float g_dbc[(size_t)MM * 64];            // x-proj output (dt|B|C) fp32
__device__ float g_csum[(size_t)MM * EDIM];         // within-chunk cumsum(delta)
__device__ float g_hstate[(size_t)BB * NCHUNK * EDIM * NSTATE]; // h_end -> h_in
__device__ float g_meta[EDIM * 2];                  // {a0, pw} per channel
__device__ __nv_bfloat16 g_ypart[(size_t)MM * EDIM];    // local scan output bf16
__device__ __nv_bfloat16 g_u_bf[(size_t)MM * DD];       // normed input
__device__ __nv_bfloat16 g_xp_bf[(size_t)MM * EDIM];    // in-proj x half
__device__ __nv_bfloat16 g_z_bf[(size_t)MM * EDIM];     // in-proj z half
__device__ __nv_bfloat16 g_xc_bf[(size_t)MM * EDIM];    // conv+silu output
__device__ __nv_bfloat16 g_y_bf[(size_t)MM * EDIM];     // scan output
__device__ __nv_bfloat16 g_inw_bf[(size_t)NLAY * 2 * EDIM * DD];
__device__ __nv_bfloat16 g_outw_bf[(size_t)NLAY * DD * EDIM];
__device__ __nv_bfloat16 g_xprojw_bf[(size_t)NLAY * 64 * EDIM];

// ================= helpers ======================================================
__device__ __forceinline__ uint32_t smem_u32(const void* p) {
    uint32_t a;
    asm("{ .reg .u64 t; cvta.to.shared.u64 t, %1; cvt.u32.u64 %0, t; }"
        : "=r"(a) : "l"(p));
    return a;
}
#define SWZ(o) ((o) ^ (((o) >> 3) & 0x70))

__device__ __forceinline__ void cp16(uint32_t dst, const void* src) {
    asm volatile("cp.async.cg.shared.global [%0], [%1], 16;" :: "r"(dst), "l"(src));
}
__device__ __forceinline__ void cp_commit() {
    asm volatile("cp.async.commit_group;");
}
template<int N>
__device__ __forceinline__ void cp_wait() {
    asm volatile("cp.async.wait_group %0;" :: "n"(N));
}

__device__ __forceinline__ void ldsm_x4(uint32_t& r0, uint32_t& r1,
                                        uint32_t& r2, uint32_t& r3, uint32_t addr) {
    asm volatile("ldmatrix.sync.aligned.m8n8.x4.shared.b16 {%0,%1,%2,%3}, [%4];"
                 : "=r"(r0), "=r"(r1), "=r"(r2), "=r"(r3) : "r"(addr));
}
__device__ __forceinline__ void mma16816(float* d, const uint32_t* a, const uint32_t* b) {
    asm volatile("mma.sync.aligned.m16n8k16.row.col.f32.bf16.bf16.f32 "
                 "{%0,%1,%2,%3}, {%4,%5,%6,%7}, {%8,%9}, {%0,%1,%2,%3};"
                 : "+f"(d[0]), "+f"(d[1]), "+f"(d[2]), "+f"(d[3])
                 : "r"(a[0]), "r"(a[1]), "r"(a[2]), "r"(a[3]),
                   "r"(b[0]), "r"(b[1]));
}

// ================= bf16 HMMA GEMM: C[M,N] = A[M,K] @ B[N,K]^T ===================
// Tiles: BM x BN, 8 warps in MW x (8/MW) grid. 3-stage cp.async pipeline.
// EPI 0: fp32 C store.
// EPI 1: split bf16 store: n<EDIM -> xp_bf, else -> z_bf (both [M][EDIM]).
// EPI 2: C = (C + acc) * mask[m]; rows with (m % LL)==0 also copied to tail.
template<int BM, int BN, int MW, int EPI, int MINB>
__global__ __launch_bounds__(256, MINB)
void mma_gemm(const __nv_bfloat16* __restrict__ A, const __nv_bfloat16* __restrict__ Bw,
              float* __restrict__ C,
              __nv_bfloat16* __restrict__ xp_bf, __nv_bfloat16* __restrict__ z_bf,
              int M, int N, int K, int ldc, const int* __restrict__ mask,
              float* __restrict__ tail) {
    constexpr int BK = 64;
    constexpr int NW = 8 / MW;
    constexpr int WM = BM / MW;
    constexpr int WN = BN / NW;
    constexpr int MFRAG = WM / 16;
    constexpr int NFRAG = WN / 8;
    constexpr int ASZ = BM * 128;
    constexpr int BSZ = BN * 128;
    constexpr int STG = 3;

    extern __shared__ __align__(1024) char dynsmem[];
    char* sA = dynsmem;
    char* sB = dynsmem + STG * ASZ;

    int tid = threadIdx.x;
    int wid = tid >> 5, lane = tid & 31;
    int bm = blockIdx.y * BM, bn = blockIdx.x * BN;
    int wm = (wid / NW) * WM;
    int wn = (wid % NW) * WN;
    uint32_t sAb = smem_u32(sA), sBb = smem_u32(sB);

    uint32_t aBase[MFRAG];
    #pragma unroll
    for (int i = 0; i < MFRAG; i++)
        aBase[i] = (uint32_t)((wm + i * 16 + (lane & 15)) * 128 + (lane >> 4) * 16);
    uint32_t bBase[(NFRAG + 1) / 2];
    #pragma unroll
    for (int j = 0; j < NFRAG / 2; j++)
        bBase[j] = (uint32_t)((wn + j * 16 + (lane & 7) + ((lane >> 4) & 1) * 8) * 128
                              + ((lane >> 3) & 1) * 16);

    float acc[MFRAG][NFRAG][4];
    #pragma unroll
    for (int i = 0; i < MFRAG; i++)
        #pragma unroll
        for (int j = 0; j < NFRAG; j++)
            #pragma unroll
            for (int q = 0; q < 4; q++) acc[i][j][q] = 0.f;

    const int nk = K / BK;

#define LOAD_STAGE(kc, st) do {                                                 \
        _Pragma("unroll")                                                       \
        for (int i = 0; i < (BM * 8) / 256; i++) {                              \
            int idx = tid + i * 256;                                            \
            int r = idx >> 3, c8 = idx & 7;                                     \
            cp16(sAb + (st) * ASZ + SWZ((uint32_t)(r * 128 + c8 * 16)),         \
                 A + (size_t)(bm + r) * K + (kc) * 64 + c8 * 8);                \
        }                                                                       \
        _Pragma("unroll")                                                       \
        for (int i = 0; i < (BN * 8) / 256; i++) {                              \
            int idx = tid + i * 256;                                            \
            int r = idx >> 3, c8 = idx & 7;                                     \
            cp16(sBb + (st) * BSZ + SWZ((uint32_t)(r * 128 + c8 * 16)),         \
                 Bw + (size_t)(bn + r) * K + (kc) * 64 + c8 * 8);               \
        }                                                                       \
    } while (0)

    LOAD_STAGE(0, 0); cp_commit();
    LOAD_STAGE(1, 1); cp_commit();

    int st = 0;
    for (int kc = 0; kc < nk; kc++) {
        cp_wait<1>();
        __syncthreads();
        if (kc + 2 < nk) {
            int st2 = st + 2 >= STG ? st + 2 - STG : st + 2;
            LOAD_STAGE(kc + 2, st2);
        }
        cp_commit();

        uint32_t aS = sAb + st * ASZ, bS = sBb + st * BSZ;
        #pragma unroll
        for (int ks = 0; ks < 4; ks++) {
            uint32_t af[MFRAG][4];
            #pragma unroll
            for (int i = 0; i < MFRAG; i++)
                ldsm_x4(af[i][0], af[i][1], af[i][2], af[i][3],
                        aS + SWZ(aBase[i] + ks * 32));
            uint32_t bf[NFRAG][2];
            #pragma unroll
            for (int j = 0; j < NFRAG / 2; j++) {
                uint32_t r0, r1, r2, r3;
                ldsm_x4(r0, r1, r2, r3, bS + SWZ(bBase[j] + ks * 32));
                bf[j * 2][0] = r0; bf[j * 2][1] = r1;
                bf[j * 2 + 1][0] = r2; bf[j * 2 + 1][1] = r3;
            }
            #pragma unroll
            for (int i = 0; i < MFRAG; i++)
                #pragma unroll
                for (int j = 0; j < NFRAG; j++)
                    mma16816(acc[i][j], af[i], bf[j]);
        }
        st = (st + 1 == STG) ? 0 : st + 1;
    }
#undef LOAD_STAGE

    // ---- epilogue ----
    bool isz = false;
    __nv_bfloat16* OB = nullptr;
    if (EPI == 1) { isz = (bn >= EDIM); OB = isz ? z_bf : xp_bf; }
    #pragma unroll
    for (int i = 0; i < MFRAG; i++) {
        int r0 = bm + wm + i * 16 + (lane >> 2);
        int r1 = r0 + 8;
        float mk0 = 1.f, mk1 = 1.f;
        if (EPI == 2) { mk0 = (float)mask[r0]; mk1 = (float)mask[r1]; }
        #pragma unroll
        for (int j = 0; j < NFRAG; j++) {
            int c = bn + wn + j * 8 + (lane & 3) * 2;
            if (EPI == 1) {
                int cb = c - (isz ? EDIM : 0);
                __nv_bfloat162 b0 = __floats2bfloat162_rn(acc[i][j][0], acc[i][j][1]);
                __nv_bfloat162 b1 = __floats2bfloat162_rn(acc[i][j][2], acc[i][j][3]);
                *reinterpret_cast<__nv_bfloat162*>(OB + (size_t)r0 * EDIM + cb) = b0;
                *reinterpret_cast<__nv_bfloat162*>(OB + (size_t)r1 * EDIM + cb) = b1;
            } else {
                size_t i0 = (size_t)r0 * ldc + c;
                size_t i1 = (size_t)r1 * ldc + c;
                float2 v0 = make_float2(acc[i][j][0], acc[i][j][1]);
                float2 v1 = make_float2(acc[i][j][2], acc[i][j][3]);
                if (EPI == 2) {
                    float2 o0 = *reinterpret_cast<float2*>(C + i0);
                    float2 o1 = *reinterpret_cast<float2*>(C + i1);
                    v0 = make_float2((o0.x + v0.x) * mk0, (o0.y + v0.y) * mk0);
                    v1 = make_float2((o1.x + v1.x) * mk1, (o1.y + v1.y) * mk1);
                }
                *reinterpret_cast<float2*>(C + i0) = v0;
                *reinterpret_cast<float2*>(C + i1) = v1;
                if (EPI == 2 && tail != nullptr && (r0 & (LL - 1)) == 0) {
                    int bidx = r0 >> 11;
                    *reinterpret_cast<float2*>(tail + (size_t)bidx * DD + c) = v0;
                }
            }
        }
    }
}

// ---------------- rmsnorm -> bf16 ------------------------------------------------
__global__ void rmsnorm_kernel(const float* __restrict__ x,
                               const float* __restrict__ w,
                               __nv_bfloat16* __restrict__ out) {
    int m = blockIdx.x;
    int tid = threadIdx.x;
    float4 v = reinterpret_cast<const float4*>(x + (size_t)m * DD)[tid];
    float ss = v.x * v.x + v.y * v.y + v.z * v.z + v.w * v.w;
    #pragma unroll
    for (int o = 16; o; o >>= 1) ss += __shfl_xor_sync(0xffffffffu, ss, o);
    __shared__ float red[4];
    if ((tid & 31) == 0) red[tid >> 5] = ss;
    __syncthreads();
    float tot = red[0] + red[1] + red[2] + red[3];
    float rs = rsqrtf(tot * (1.0f / DD) + 1e-5f);
    float4 wv = reinterpret_cast<const float4*>(w)[tid];
    __nv_bfloat162 p0 = __floats2bfloat162_rn(v.x * rs * wv.x, v.y * rs * wv.y);
    __nv_bfloat162 p1 = __floats2bfloat162_rn(v.z * rs * wv.z, v.w * rs * wv.w);
    uint2 o2 = make_uint2(*reinterpret_cast<uint32_t*>(&p0),
                          *reinterpret_cast<uint32_t*>(&p1));
    reinterpret_cast<uint2*>(out + (size_t)m * DD)[tid] = o2;
}

// ---------------- depthwise causal conv (K=4) + bias + silu (bf16 in/out) -------
__global__ void conv_silu_kernel(const __nv_bfloat16* __restrict__ xp,
                                 const float* __restrict__ w,
                                 const float* __restrict__ b,
                                 __nv_bfloat16* __restrict__ xc_bf) {
    int id = blockIdx.x * blockDim.x + threadIdx.x;
    if (id >= MM * EDIM) return;
    int e = id & (EDIM - 1);
    int mt = id >> 10;
    int t = mt & (LL - 1);
    float w0 = w[e*4+0], w1 = w[e*4+1], w2 = w[e*4+2], w3 = w[e*4+3];
    const __nv_bfloat16* base = xp + (size_t)mt * EDIM + e;
    float x0 = (t >= 3) ? __bfloat162float(base[-3 * EDIM]) : 0.f;
    float x1 = (t >= 2) ? __bfloat162float(base[-2 * EDIM]) : 0.f;
    float x2 = (t >= 1) ? __bfloat162float(base[-1 * EDIM]) : 0.f;
    float x3 = __bfloat162float(base[0]);
    float acc = b[e] + w0 * x0 + w1 * x1 + w2 * x2 + w3 * x3;
    acc = acc * (1.f / (1.f + __expf(-acc)));
    xc_bf[id] = __float2bfloat16(acc);
}

// ================= chunk-parallel selective scan =================================
#define SCAN_CH 64
#define S1_SMEM ((SCAN_CH * 128 + SCAN_CH * 64) * (int)sizeof(float))   // 48 KB

__global__ void scan_part1(const __nv_bfloat16* __restrict__ xcb,
                           const float* __restrict__ dbc,
                           const float* __restrict__ A_log,
                           const float* __restrict__ dtw,   // [EDIM][32]
                           const float* __restrict__ dtb,   // [EDIM]
                           __nv_bfloat16* __restrict__ ypart,
                           float* __restrict__ csum,
                           float* __restrict__ hstate) {
    extern __shared__ float sh[];
    float* sX   = sh;                      // [64][128]
    float* sDBC = sh + SCAN_CH * 128;      // [64][64]  (dt | B | C)

    int b = blockIdx.y, c = blockIdx.z;
    int tid = threadIdx.x;
    int e0 = blockIdx.x * 128;
    int e = e0 + tid;

    float a[NSTATE];
    #pragma unroll
    for (int n = 0; n < NSTATE; n++) a[n] = -__expf(A_log[(size_t)e * NSTATE + n]);
    float a0 = a[0];
    bool pw = true;
    #pragma unroll
    for (int n = 0; n < NSTATE; n++)
        pw = pw && (fabsf(a[n] - a0 * (n + 1)) <= 1e-5f * fabsf(a[n]) + 1e-12f);

    float4 w4[8];
    #pragma unroll
    for (int q = 0; q < 8; q++)
        w4[q] = reinterpret_cast<const float4*>(dtw + (size_t)e * RRANK)[q];
    float bias = dtb[e];

    float h[NSTATE];
    #pragma unroll
    for (int n = 0; n < NSTATE; n++) h[n] = 0.f;
    float cs = 0.f;

    const float* dbcb = dbc + (size_t)b * LL * 64;
    int tbase = c * CHLEN;

    for (int t0 = tbase; t0 < tbase + CHLEN; t0 += SCAN_CH) {
        __syncthreads();
        for (int i = tid; i < SCAN_CH * 16; i += 128) {
            int r = i >> 4, c4 = i & 15;
            reinterpret_cast<float4*>(sDBC)[i] =
                reinterpret_cast<const float4*>(dbcb + (size_t)(t0 + r) * 64)[c4];
        }
        for (int g = tid; g < SCAN_CH * 16; g += 128) {
            int r = g >> 4, c8 = g & 15;
            size_t m = (size_t)(b * LL + t0 + r);
            uint4 vx = *reinterpret_cast<const uint4*>(xcb + m * EDIM + e0 + c8 * 8);
            const __nv_bfloat162* px = reinterpret_cast<const __nv_bfloat162*>(&vx);
            int o = r * 128 + c8 * 8;
            #pragma unroll
            for (int k = 0; k < 4; k++) {
                float2 fx = __bfloat1622float2(px[k]);
                sX[o + 2*k] = fx.x; sX[o + 2*k + 1] = fx.y;
            }
        }
        __syncthreads();

        for (int i = 0; i < SCAN_CH; i++) {
            const float* row = sDBC + i * 64;
            float s = bias;
            #pragma unroll
            for (int q = 0; q < 8; q++) {
                float4 dt4 = reinterpret_cast<const float4*>(row)[q];
                s += w4[q].x * dt4.x + w4[q].y * dt4.y
                   + w4[q].z * dt4.z + w4[q].w * dt4.w;
            }
            float d = (s > 20.f) ? s : log1pf(__expf(s));
            float xv = sX[i * 128 + tid];
            float du = d * xv;
            cs += d;
            float dA[NSTATE];
            if (pw) {
                float p = __expf(a0 * d);
                dA[0] = p;
                #pragma unroll
                for (int n = 1; n < NSTATE; n++) dA[n] = dA[n - 1] * p;
            } else {
                #pragma unroll
                for (int n = 0; n < NSTATE; n++) dA[n] = __expf(a[n] * d);
            }
            float yv = 0.f, yv2 = 0.f;
            const float* bc = row + 32;
            #pragma unroll
            for (int n = 0; n < NSTATE; n++) {
                h[n] = dA[n] * h[n] + du * bc[n];
                float cv = bc[16 + n];
                if (n & 1) yv2 += h[n] * cv; else yv += h[n] * cv;
            }
            size_t idx = (size_t)(b * LL + t0 + i) * EDIM + e;
            ypart[idx] = __float2bfloat16(yv + yv2);
            csum[idx] = cs;
        }
    }

    float* hp = hstate + ((size_t)(b * NCHUNK + c) * EDIM + e) * NSTATE;
    #pragma unroll
    for (int q = 0; q < 4; q++)
        reinterpret_cast<float4*>(hp)[q] =
            make_float4(h[q*4+0], h[q*4+1], h[q*4+2], h[q*4+3]);
}

// S2: sequential combine across chunks; hstate becomes h_in (state at chunk entry).
__global__ void scan_combine(const float* __restrict__ csum,
                             const float* __restrict__ A_log,
                             float* __restrict__ hstate,
                             float* __restrict__ meta) {
    int id = blockIdx.x * blockDim.x + threadIdx.x;   // b*EDIM + e
    if (id >= BB * EDIM) return;
    int b = id >> 10, e = id & (EDIM - 1);

    float a[NSTATE];
    #pragma unroll
    for (int n = 0; n < NSTATE; n++) a[n] = -__expf(A_log[(size_t)e * NSTATE + n]);
    float a0 = a[0];
    bool pw = true;
    #pragma unroll
    for (int n = 0; n < NSTATE; n++)
        pw = pw && (fabsf(a[n] - a0 * (n + 1)) <= 1e-5f * fabsf(a[n]) + 1e-12f);
    if (b == 0) { meta[e * 2] = a0; meta[e * 2 + 1] = pw ? 1.f : 0.f; }

    float carry[NSTATE];
    #pragma unroll
    for (int n = 0; n < NSTATE; n++) carry[n] = 0.f;

    for (int c = 0; c < NCHUNK; c++) {
        float SE = csum[(size_t)(b * LL + c * CHLEN + CHLEN - 1) * EDIM + e];
        float f[NSTATE];
        if (pw) {
            float p = __expf(a0 * SE);
            f[0] = p;
            #pragma unroll
            for (int n = 1; n < NSTATE; n++) f[n] = f[n - 1] * p;
        } else {
            #pragma unroll
            for (int n = 0; n < NSTATE; n++) f[n] = __expf(a[n] * SE);
        }
        float* hp = hstate + ((size_t)(b * NCHUNK + c) * EDIM + e) * NSTATE;
        #pragma unroll
        for (int q = 0; q < 4; q++) {
            float4 he = reinterpret_cast<float4*>(hp)[q];
            reinterpret_cast<float4*>(hp)[q] =
                make_float4(carry[q*4+0], carry[q*4+1], carry[q*4+2], carry[q*4+3]);
            carry[q*4+0] = f[q*4+0] * carry[q*4+0] + he.x;
            carry[q*4+1] = f[q*4+1] * carry[q*4+1] + he.y;
            carry[q*4+2] = f[q*4+2] * carry[q*4+2] + he.z;
            carry[q*4+3] = f[q*4+3] * carry[q*4+3] + he.w;
        }
    }
}

// S3: fully parallel correction + D + gating -> bf16 y. 2 e-elements per thread.
__global__ void scan_part2(const __nv_bfloat16* __restrict__ ypart,
                           const float* __restrict__ csum,
                           const float* __restrict__ dbc,
                           const __nv_bfloat16* __restrict__ xcb,
                           const __nv_bfloat16* __restrict__ zb,
                           const float* __restrict__ A_log,
                           const float* __restrict__ Dp,
                           const float* __restrict__ hstate,
                           const float* __restrict__ meta,
                           __nv_bfloat16* __restrict__ y) {
    __shared__ float sC[NSTATE];
    size_t p = (size_t)blockIdx.x * 256 + threadIdx.x;  // pair index
    size_t id = p * 2;
    int e = (int)(id & (EDIM - 1));
    size_t m = id >> 10;
    int b = (int)(m >> 11);
    int t = (int)(m & (LL - 1));
    int c = t >> 7;

    if (threadIdx.x < NSTATE) sC[threadIdx.x] = dbc[m * 64 + 48 + threadIdx.x];
    __syncthreads();

    float2 S = *reinterpret_cast<const float2*>(csum + id);
    float2 dp = *reinterpret_cast<const float2*>(Dp + e);
    float a0_0 = meta[e * 2],     a0_1 = meta[e * 2 + 2];
    bool pw0 = meta[e * 2 + 1] > 0.5f, pw1 = meta[e * 2 + 3] > 0.5f;

    float f0[NSTATE], f1[NSTATE];
    if (pw0) {
        float pp = __expf(a0_0 * S.x);
        f0[0] = pp;
        #pragma unroll
        for (int n = 1; n < NSTATE; n++) f0[n] = f0[n - 1] * pp;
    } else {
        #pragma unroll
        for (int n = 0; n < NSTATE; n++)
            f0[n] = __expf(-__expf(A_log[(size_t)e * NSTATE + n]) * S.x);
    }
    if (pw1) {
        float pp = __expf(a0_1 * S.y);
        f1[0] = pp;
        #pragma unroll
        for (int n = 1; n < NSTATE; n++) f1[n] = f1[n - 1] * pp;
    } else {
        #pragma unroll
        for (int n = 0; n < NSTATE; n++)
            f1[n] = __expf(-__expf(A_log[(size_t)(e + 1) * NSTATE + n]) * S.y);
    }

    const float* hp0 = hstate + ((size_t)(b * NCHUNK + c) * EDIM + e) * NSTATE;
    float ca = 0.f, cb2 = 0.f;
    #pragma unroll
    for (int q = 0; q < 4; q++) {
        float4 h0 = reinterpret_cast<const float4*>(hp0)[q];
        float4 h1 = reinterpret_cast<const float4*>(hp0 + NSTATE)[q];
        ca  += sC[q*4+0] * f0[q*4+0] * h0.x + sC[q*4+1] * f0[q*4+1] * h0.y
             + sC[q*4+2] * f0[q*4+2] * h0.z + sC[q*4+3] * f0[q*4+3] * h0.w;
        cb2 += sC[q*4+0] * f1[q*4+0] * h1.x + sC[q*4+1] * f1[q*4+1] * h1.y
             + sC[q*4+2] * f1[q*4+2] * h1.z + sC[q*4+3] * f1[q*4+3] * h1.w;
    }
    float2 yp = __bfloat1622float2(*reinterpret_cast<const __nv_bfloat162*>(ypart + id));
    float2 xv = __bfloat1622float2(*reinterpret_cast<const __nv_bfloat162*>(xcb + id));
    float2 zv = __bfloat1622float2(*reinterpret_cast<const __nv_bfloat162*>(zb + id));
    float y0 = (yp.x + ca  + dp.x * xv.x) * (zv.x / (1.f + __expf(-zv.x)));
    float y1 = (yp.y + cb2 + dp.y * xv.y) * (zv.y / (1.f + __expf(-zv.y)));
    *reinterpret_cast<__nv_bfloat162*>(y + id) = __floats2bfloat162_rn(y0, y1);
}

// ---------------- misc -----------------------------------------------------------
__global__ void init_x(const float* __restrict__ x, const int* __restrict__ mask,
                       float* __restrict__ xb) {
    int id = blockIdx.x * blockDim.x + threadIdx.x;
    if (id < MM * DD) xb[id] = x[id] * (float)mask[id >> 9];
}

__global__ void cvt_weights(const float* __restrict__ s1, int n1,
                            const float* __restrict__ s2, int n2,
                            const float* __restrict__ s3, int n3,
                            __nv_bfloat16* __restrict__ d1,
                            __nv_bfloat16* __restrict__ d2,
                            __nv_bfloat16* __restrict__ d3) {
    int id = blockIdx.x * blockDim.x + threadIdx.x;
    if (id < n1) d1[id] = __float2bfloat16(s1[id]);
    else if (id < n1 + n2) d2[id - n1] = __float2bfloat16(s2[id - n1]);
    else if (id < n1 + n2 + n3) d3[id - n1 - n2] = __float2bfloat16(s3[id - n1 - n2]);
}

// ---------------- launch ---------------------------------------------------------
extern "C" void kernel_launch(void* const* d_in, const int* in_sizes, int n_in,
                              void* d_out, int out_size) {
    const float* x        = (const float*)d_in[0];
    const int*   mask     = (const int*)d_in[1];
    const float* norm_w   = (const float*)d_in[2];
    const float* in_w     = (const float*)d_in[3];
    const float* conv_w   = (const float*)d_in[4];
    const float* conv_b   = (const float*)d_in[5];
    const float* xproj_w  = (const float*)d_in[6];
    const float* dtproj_w = (const float*)d_in[7];
    const float* dtproj_b = (const float*)d_in[8];
    const float* A_log    = (const float*)d_in[9];
    const float* D_param  = (const float*)d_in[10];
    const float* out_w    = (const float*)d_in[11];

    float* xb   = (float*)d_out;
    float* tail = xb + (size_t)MM * DD;

    float *dbcp, *csump, *hstatep, *metap;
    __nv_bfloat16 *ypartp, *ubf, *xpbf, *zbf, *xcbf, *ybf, *inwbf, *outwbf, *xprojwbf;
    cudaGetSymbolAddress((void**)&dbcp, g_dbc);
    cudaGetSymbolAddress((void**)&ypartp, g_ypart);
    cudaGetSymbolAddress((void**)&csump, g_csum);
    cudaGetSymbolAddress((void**)&hstatep, g_hstate);
    cudaGetSymbolAddress((void**)&metap, g_meta);
    cudaGetSymbolAddress((void**)&ubf, g_u_bf);
    cudaGetSymbolAddress((void**)&xpbf, g_xp_bf);
    cudaGetSymbolAddress((void**)&zbf, g_z_bf);
    cudaGetSymbolAddress((void**)&xcbf, g_xc_bf);
    cudaGetSymbolAddress((void**)&ybf, g_y_bf);
    cudaGetSymbolAddress((void**)&inwbf, g_inw_bf);
    cudaGetSymbolAddress((void**)&outwbf, g_outw_bf);
    cudaGetSymbolAddress((void**)&xprojwbf, g_xprojw_bf);

    cudaFuncSetAttribute(scan_part1,
                         cudaFuncAttributeMaxDynamicSharedMemorySize, S1_SMEM);
    constexpr int SM_BIG = 3 * (128 * 128 + 64 * 128);   // 72 KB (BM=128, BN=64)
    constexpr int SM_XP  = 3 * (64 * 128 + 64 * 128);    // 48 KB (BM=64, BN=64)
    cudaFuncSetAttribute((const void*)mma_gemm<128, 64, 4, 1, 3>,
                         cudaFuncAttributeMaxDynamicSharedMemorySize, SM_BIG);
    cudaFuncSetAttribute((const void*)mma_gemm<128, 64, 4, 2, 3>,
                         cudaFuncAttributeMaxDynamicSharedMemorySize, SM_BIG);
    cudaFuncSetAttribute((const void*)mma_gemm<64, 64, 2, 0, 3>,
                         cudaFuncAttributeMaxDynamicSharedMemorySize, SM_XP);

    init_x<<<(MM * DD + 255) / 256, 256>>>(x, mask, xb);

    {
        int n1 = NLAY * 2 * EDIM * DD;
        int n2 = NLAY * DD * EDIM;
        int n3 = NLAY * 64 * EDIM;
        cvt_weights<<<(n1 + n2 + n3 + 255) / 256, 256>>>(
            in_w, n1, out_w, n2, xproj_w, n3, inwbf, outwbf, xprojwbf);
    }

    for (int l = 0; l < NLAY; l++) {
        rmsnorm_kernel<<<MM, 128>>>(xb, norm_w + l * DD, ubf);

        // xz = u @ in_w^T : M=8192, N=2048, K=512 -> split bf16 xp/z
        mma_gemm<128, 64, 4, 1, 3><<<dim3(2 * EDIM / 64, MM / 128), 256, SM_BIG>>>(
            ubf, inwbf + (size_t)l * 2 * EDIM * DD, nullptr, xpbf, zbf,
            MM, 2 * EDIM, DD, 0, nullptr, nullptr);

        conv_silu_kernel<<<(MM * EDIM + 255) / 256, 256>>>(
            xpbf, conv_w + (size_t)l * EDIM * KCONV, conv_b + l * EDIM, xcbf);

        // dbc = xc @ xproj_w^T : M=8192, N=64, K=1024 (fp32 out)
        mma_gemm<64, 64, 2, 0, 3><<<dim3(1, MM / 64), 256, SM_XP>>>(
            xcbf, xprojwbf + (size_t)l * 64 * EDIM, dbcp, nullptr, nullptr,
            MM, 64, EDIM, 64, nullptr, nullptr);

        // chunk-parallel scan (delta computed inline in part1)
        scan_part1<<<dim3(EDIM / 128, BB, NCHUNK), 128, S1_SMEM>>>(
            xcbf, dbcp, A_log + (size_t)l * EDIM * NSTATE,
            dtproj_w + (size_t)l * EDIM * RRANK, dtproj_b + l * EDIM,
            ypartp, csump, hstatep);
        scan_combine<<<(BB * EDIM + 255) / 256, 256>>>(
            csump, A_log + (size_t)l * EDIM * NSTATE, hstatep, metap);
        scan_part2<<<(int)(((size_t)MM * EDIM / 2) / 256), 256>>>(
            ypartp, csump, dbcp, xcbf, zbf,
            A_log + (size_t)l * EDIM * NSTATE, D_param + l * EDIM,
            hstatep, metap, ybf);

        // x = (x + y @ out_w^T) * mask ; last layer also writes tail rows
        mma_gemm<128, 64, 4, 2, 3><<<dim3(DD / 64, MM / 128), 256, SM_BIG>>>(
            ybf, outwbf + (size_t)l * DD * EDIM, xb, nullptr, nullptr,
            MM, DD, EDIM, DD, mask, (l == NLAY - 1) ? tail : nullptr);
    }
}